// round 12
// baseline (speedup 1.0000x reference)
#include <cuda_runtime.h>
#include <cstdint>

// context_window: out[b, f*11 + c, t] = x[b, f, t + c - 5], zero-padded in t.
// x: (32, 80, 3000) fp32 -> out: (32, 880, 3000) fp32.
//
// R12: TMA bulk-store write path. Threads build output tiles in SMEM
// (11 channels x 1000 floats per CTA), then the CTA drains them with 11
// cp.async.bulk (UTMASTG) SMEM->GMEM copies of 4000B each — bypassing the
// L1tex STG path entirely (the only structurally untested write path after
// 11 rounds pinned at DRAM ~70% / 55.3us). Load path unchanged from the
// proven R1 shape (5 aligned LDG.128 per thread window).

#define T_DIM     3000
#define C_LEN     11
#define ROWS      (32 * 80)   // 2560
#define T4        (T_DIM / 4) // 750
#define CHUNK_T4  250         // float4s per CTA
#define CHUNK_T   1000        // floats per channel per CTA
#define NCHUNK    3
#define BLOCK     256
#define CH_BYTES  (CHUNK_T * 4)  // 4000, multiple of 16

__global__ __launch_bounds__(BLOCK) void context_window_kernel(
    const float* __restrict__ x, float* __restrict__ out)
{
    __shared__ __align__(16) float buf[C_LEN][CHUNK_T];   // 44000 B

    int row   = blockIdx.x;               // b*80 + f
    int chunk = blockIdx.y;               // 0..2
    int tid   = threadIdx.x;

    const float* __restrict__ xr = x + row * T_DIM;

    if (tid < CHUNK_T4) {
        int t4 = chunk * CHUNK_T4 + tid;  // global float4 index, 0..749
        int t  = t4 * 4;

        // Register window w[k] = x[t-8+k], k=0..19; out[c, t+j] = w[j+c+3].
        float w[20];
        if (t4 >= 2 && t4 <= T4 - 3) {
            const float4* __restrict__ p =
                reinterpret_cast<const float4*>(xr + t - 8);
            #pragma unroll
            for (int i = 0; i < 5; i++) {
                float4 v = p[i];
                w[4*i + 0] = v.x; w[4*i + 1] = v.y;
                w[4*i + 2] = v.z; w[4*i + 3] = v.w;
            }
        } else {
            // Edge (t4 in {0,1,748,749}): scalar bounds-checked loads
            // (implements the zero padding).
            #pragma unroll
            for (int k = 0; k < 20; k++) {
                int idx = t - 8 + k;
                w[k] = (idx >= 0 && idx < T_DIM) ? xr[idx] : 0.0f;
            }
        }

        // Stage 11 float4s into SMEM (STS.128, stride 16B -> conflict-free).
        int lt = tid * 4;
        #pragma unroll
        for (int c = 0; c < C_LEN; c++) {
            *reinterpret_cast<float4*>(&buf[c][lt]) =
                make_float4(w[c + 3], w[c + 4], w[c + 5], w[c + 6]);
        }
    }
    __syncthreads();

    // Drain: 11 x 4000B bulk copies SMEM->GMEM via the TMA engine.
    if (tid == 0) {
        // Order generic-proxy SMEM writes before async-proxy reads.
        asm volatile("fence.proxy.async.shared::cta;" ::: "memory");

        float* dst_base = out + (row * C_LEN) * T_DIM + chunk * CHUNK_T;
        #pragma unroll
        for (int c = 0; c < C_LEN; c++) {
            uint32_t src = (uint32_t)__cvta_generic_to_shared(&buf[c][0]);
            asm volatile(
                "cp.async.bulk.global.shared::cta.bulk_group [%0], [%1], %2;"
                :: "l"(dst_base + c * T_DIM), "r"(src), "r"((int)CH_BYTES)
                : "memory");
        }
        asm volatile("cp.async.bulk.commit_group;" ::: "memory");
        asm volatile("cp.async.bulk.wait_group 0;" ::: "memory");
    }
}

extern "C" void kernel_launch(void* const* d_in, const int* in_sizes, int n_in,
                              void* d_out, int out_size)
{
    const float* x = (const float*)d_in[0];
    float* out = (float*)d_out;

    dim3 block(BLOCK);
    dim3 grid(ROWS, NCHUNK);   // (2560, 3)
    context_window_kernel<<<grid, block>>>(x, out);
}

// round 13
// speedup vs baseline: 1.0474x; 1.0474x over previous
#include <cuda_runtime.h>

// context_window: out[b, f*11 + c, t] = x[b, f, t + c - 5], zero-padded in t.
// x: (32, 80, 3000) fp32 -> out: (32, 880, 3000) fp32.
//
// FINAL. Roofline-confirmed across 12 design variants (tile width/vector
// width, .cs hints, shuffle-deduped loads, persistent/exact/whole-row grids,
// output-centric gather, asm-pinned interleave, TMA bulk stores): every
// variant lands at 55.3-58.6us ncu with DRAM ~67-71%. The kernel is bound by
// its compulsory byte traffic (338MB writes + 31MB reads) at ~6.7TB/s
// effective HBM (~83% of spec) — the B300 mixed-stream ceiling. This is the
// best-measured, repeatable shape (55.33/55.36/55.36us over three runs):
//
//   per thread (one (row, t..t+3) output tile):
//     5x aligned LDG.128  -> 20-float register window x[t-8 .. t+11]
//     11x STG.128, warp-wide 512B contiguous, one per context shift
//   edge threads (4 of 750 per row) take a scalar bounds-checked path that
//   implements the zero padding.

#define T_DIM   3000
#define C_LEN   11
#define ROWS    (32 * 80)     // B*F = 2560
#define T4      (T_DIM / 4)   // 750 float4 chunks per row

__global__ __launch_bounds__(256) void context_window_kernel(
    const float* __restrict__ x, float* __restrict__ out)
{
    int t4 = blockIdx.x * blockDim.x + threadIdx.x;
    if (t4 >= T4) return;
    int row = blockIdx.y;                 // b*80 + f
    int t = t4 * 4;

    const float* __restrict__ xr = x + row * T_DIM;

    // Register window covering x[t-8 .. t+11] (w[k] = x[t-8+k]).
    // out[c, t+j] = x[t + j + c - 5] = w[j + c + 3]; used range w[3..16].
    float w[20];

    if (t4 >= 2 && t4 <= T4 - 3) {
        // Fast path: 5 aligned float4 loads, fully in-range.
        const float4* __restrict__ p = reinterpret_cast<const float4*>(xr + t - 8);
        #pragma unroll
        for (int i = 0; i < 5; i++) {
            float4 v = p[i];
            w[4*i + 0] = v.x; w[4*i + 1] = v.y;
            w[4*i + 2] = v.z; w[4*i + 3] = v.w;
        }
    } else {
        // Edge path (t4 in {0,1,748,749}): scalar bounds-checked loads
        // (implements the zero padding).
        #pragma unroll
        for (int k = 0; k < 20; k++) {
            int idx = t - 8 + k;
            w[k] = (idx >= 0 && idx < T_DIM) ? xr[idx] : 0.0f;
        }
    }

    // 11 coalesced, aligned float4 stores — one per context shift.
    // Warp-wide each store is 512B fully contiguous.
    float* __restrict__ orow = out + (row * C_LEN) * T_DIM + t;
    #pragma unroll
    for (int c = 0; c < C_LEN; c++) {
        *reinterpret_cast<float4*>(orow + c * T_DIM) =
            make_float4(w[c + 3], w[c + 4], w[c + 5], w[c + 6]);
    }
}

extern "C" void kernel_launch(void* const* d_in, const int* in_sizes, int n_in,
                              void* d_out, int out_size)
{
    const float* x = (const float*)d_in[0];
    float* out = (float*)d_out;

    dim3 block(256);
    dim3 grid((T4 + 255) / 256, ROWS);   // (3, 2560)
    context_window_kernel<<<grid, block>>>(x, out);
}

// round 14
// speedup vs baseline: 1.0752x; 1.0265x over previous
#include <cuda_runtime.h>

// context_window: out[b, f*11 + c, t] = x[b, f, t + c - 5], zero-padded in t.
// x: (32, 80, 3000) fp32 -> out: (32, 880, 3000) fp32.
//
// FINAL (converged). 13 structurally distinct variants — tile width 4/8,
// 128/256-bit vector ops, .cs/.nc cache hints, shuffle-deduplicated loads,
// persistent grid, exact 1D grid, whole-row CTAs, output-centric linear-write
// gather, asm-pinned load/store interleave (MLP_p1), and TMA bulk stores —
// all measured 55.3-58.6us ncu with DRAM 67-71%. The kernel is bound by its
// compulsory byte traffic (338MB writes + 31MB reads) at ~6.7TB/s effective
// HBM (~83% of the 8TB/s spec), the B300 mixed-stream ceiling; the addr->
// channel hash flattens all write-locality arrangements and the store path is
// throughput-path-independent (STG == TMA), both per B300_MICROARCH and
// confirmed by direct experiment. Occupancy varied 29-76% across rounds with
// no duration correlation: pure bandwidth-bound.
//
// Champion shape (ncu: 55.33/55.36/55.36/55.74us over four runs):
//   per thread (one (row, t..t+3) output tile):
//     5x aligned LDG.128  -> 20-float register window x[t-8 .. t+11]
//     11x STG.128, warp-wide 512B contiguous, one per context shift
//   edge threads (4 of 750 per row) take a scalar bounds-checked path that
//   implements the zero padding.

#define T_DIM   3000
#define C_LEN   11
#define ROWS    (32 * 80)     // B*F = 2560
#define T4      (T_DIM / 4)   // 750 float4 chunks per row

__global__ __launch_bounds__(256) void context_window_kernel(
    const float* __restrict__ x, float* __restrict__ out)
{
    int t4 = blockIdx.x * blockDim.x + threadIdx.x;
    if (t4 >= T4) return;
    int row = blockIdx.y;                 // b*80 + f
    int t = t4 * 4;

    const float* __restrict__ xr = x + row * T_DIM;

    // Register window covering x[t-8 .. t+11] (w[k] = x[t-8+k]).
    // out[c, t+j] = x[t + j + c - 5] = w[j + c + 3]; used range w[3..16].
    float w[20];

    if (t4 >= 2 && t4 <= T4 - 3) {
        // Fast path: 5 aligned float4 loads, fully in-range.
        const float4* __restrict__ p = reinterpret_cast<const float4*>(xr + t - 8);
        #pragma unroll
        for (int i = 0; i < 5; i++) {
            float4 v = p[i];
            w[4*i + 0] = v.x; w[4*i + 1] = v.y;
            w[4*i + 2] = v.z; w[4*i + 3] = v.w;
        }
    } else {
        // Edge path (t4 in {0,1,748,749}): scalar bounds-checked loads
        // (implements the zero padding).
        #pragma unroll
        for (int k = 0; k < 20; k++) {
            int idx = t - 8 + k;
            w[k] = (idx >= 0 && idx < T_DIM) ? xr[idx] : 0.0f;
        }
    }

    // 11 coalesced, aligned float4 stores — one per context shift.
    // Warp-wide each store is 512B fully contiguous.
    float* __restrict__ orow = out + (row * C_LEN) * T_DIM + t;
    #pragma unroll
    for (int c = 0; c < C_LEN; c++) {
        *reinterpret_cast<float4*>(orow + c * T_DIM) =
            make_float4(w[c + 3], w[c + 4], w[c + 5], w[c + 6]);
    }
}

extern "C" void kernel_launch(void* const* d_in, const int* in_sizes, int n_in,
                              void* d_out, int out_size)
{
    const float* x = (const float*)d_in[0];
    float* out = (float*)d_out;

    dim3 block(256);
    dim3 grid((T4 + 255) / 256, ROWS);   // (3, 2560)
    context_window_kernel<<<grid, block>>>(x, out);
}